// round 1
// baseline (speedup 1.0000x reference)
#include <cuda_runtime.h>
#include <cstdint>

// Problem constants
#define BATCH   128
#define NP      4096
#define DIN     256
#define DM      256
#define NHEADS  4
#define DH      64
#define HIDN    1024
#define ROWS    (BATCH*NP)          // 524288

// ---------------- scratch (device globals: no allocations allowed) ----------
__device__ float g_kv[268435456];   // [ROWS][512]  k(0:256, pre-scaled x2) | v(256:512)  (1 GiB)
__device__ float g_mu[ROWS];
__device__ float g_rstd[ROWS];
__device__ float g_W2[DIN*512];     // g ⊙ [Wk|Wv]
__device__ float g_u[512];          // sum_c g[c]*W[c][j]
__device__ float g_w0[512];         // sum_c b[c]*W[c][j]
__device__ float g_q[BATCH*DM];
__device__ float g_att[BATCH*DM];
__device__ float g_rep[BATCH*DM];
__device__ float g_new[BATCH*DM];
__device__ float g_hbuf[BATCH*HIDN];
__device__ float g_sig[BATCH*NHEADS*NP];  // last-step sigmoids (+eps)
__device__ float g_den[BATCH*NHEADS];

// ---------------- helpers ----------------------------------------------------
__device__ __forceinline__ void ffma2(unsigned long long& d, unsigned long long a, unsigned long long b){
    asm("fma.rn.f32x2 %0, %1, %2, %0;" : "+l"(d) : "l"(a), "l"(b));
}
__device__ __forceinline__ unsigned long long dupf(float x){
    unsigned long long r; unsigned u = __float_as_uint(x);
    asm("mov.b64 %0, {%1, %1};" : "=l"(r) : "r"(u));
    return r;
}
__device__ __forceinline__ float pickf(unsigned long long v, int hi){
    return __uint_as_float(hi ? (unsigned)(v >> 32) : (unsigned)v);
}

// ---------------- prep: fold LN gamma into weights ---------------------------
__global__ void k_prep(const float* __restrict__ Wk, const float* __restrict__ Wv,
                       const float* __restrict__ gin, const float* __restrict__ bin){
    int j = blockIdx.x*256 + threadIdx.x;            // 0..511
    const float* W = (j < 256) ? (Wk + j) : (Wv + (j - 256));
    float u = 0.f, w0 = 0.f;
    for (int c = 0; c < 256; c++){
        float wv = W[c*256];
        float wg = gin[c]*wv;
        g_W2[c*512 + j] = wg;
        u  += wg;
        w0 += bin[c]*wv;
    }
    g_u[j] = u; g_w0[j] = w0;
}

// ---------------- rep init: reparameterized latent ---------------------------
__global__ void k_rep0(const float* __restrict__ eps, const float* __restrict__ mu0,
                       const float* __restrict__ lv){
    int i = blockIdx.x*256 + threadIdx.x;            // 32768
    int d = i & 255;
    g_rep[i] = mu0[d] + __expf(0.5f*lv[d])*eps[i];
}

// ---------------- per-row mean / rstd of inputs ------------------------------
__global__ __launch_bounds__(256) void k_rowstats(const float4* __restrict__ inp){
    int row  = blockIdx.x*8 + (threadIdx.x >> 5);
    int lane = threadIdx.x & 31;
    const float4* p = inp + (size_t)row*64;
    float4 v1 = p[lane], v2 = p[lane+32];
    float s  = v1.x+v1.y+v1.z+v1.w + v2.x+v2.y+v2.z+v2.w;
    float ss = v1.x*v1.x+v1.y*v1.y+v1.z*v1.z+v1.w*v1.w
             + v2.x*v2.x+v2.y*v2.y+v2.z*v2.z+v2.w*v2.w;
    #pragma unroll
    for (int o = 16; o; o >>= 1){
        s  += __shfl_xor_sync(0xffffffffu, s,  o);
        ss += __shfl_xor_sync(0xffffffffu, ss, o);
    }
    if (lane == 0){
        float mu  = s*(1.f/256.f);
        float var = ss*(1.f/256.f) - mu*mu;
        g_mu[row]   = mu;
        g_rstd[row] = rsqrtf(var + 1e-5f);
    }
}

// ---------------- big GEMM: kv = LN(x) @ [Wk|Wv]  (LN folded) ----------------
// C[524288 x 512] = x @ W2, epilogue applies rstd/mu rank-1 correction + k*2.
__global__ __launch_bounds__(256,2) void k_gemm_kv(const float* __restrict__ A){
    __shared__ float As[32][132];     // [k][row] transposed, pad 4
    __shared__ float Bs[32][64];
    const int tid = threadIdx.x;
    const int tx = tid & 15, ty = tid >> 4;
    const int row0 = blockIdx.y * 128;
    const int col0 = blockIdx.x * 64;
    unsigned long long acc[4][4];
    #pragma unroll
    for (int p = 0; p < 4; p++)
        #pragma unroll
        for (int q = 0; q < 4; q++) acc[p][q] = 0ull;

    const int lr = tid >> 3, lc = tid & 7;     // A loader: 32 rows x 8 f4-cols
    const int br = tid >> 4, bc = tid & 15;    // B loader: 16 rows x 16 f4-cols

    #pragma unroll 1
    for (int k0 = 0; k0 < 256; k0 += 32){
        #pragma unroll
        for (int p = 0; p < 4; p++){
            float4 v = *(const float4*)(A + (size_t)(row0 + lr + p*32)*256 + k0 + lc*4);
            As[lc*4+0][lr+p*32] = v.x; As[lc*4+1][lr+p*32] = v.y;
            As[lc*4+2][lr+p*32] = v.z; As[lc*4+3][lr+p*32] = v.w;
        }
        #pragma unroll
        for (int p = 0; p < 2; p++){
            float4 v = *(const float4*)(g_W2 + (k0 + br + p*16)*512 + col0 + bc*4);
            *(float4*)&Bs[br + p*16][bc*4] = v;
        }
        __syncthreads();
        #pragma unroll
        for (int kk = 0; kk < 32; kk++){
            ulonglong2 a0 = *(const ulonglong2*)&As[kk][ty*8];      // row pairs 0-1,2-3
            ulonglong2 a1 = *(const ulonglong2*)&As[kk][ty*8 + 4];  // row pairs 4-5,6-7
            float4 bv = *(const float4*)&Bs[kk][tx*4];
            unsigned long long bd0 = dupf(bv.x), bd1 = dupf(bv.y);
            unsigned long long bd2 = dupf(bv.z), bd3 = dupf(bv.w);
            unsigned long long ap[4] = {a0.x, a0.y, a1.x, a1.y};
            #pragma unroll
            for (int p = 0; p < 4; p++){
                ffma2(acc[p][0], ap[p], bd0);
                ffma2(acc[p][1], ap[p], bd1);
                ffma2(acc[p][2], ap[p], bd2);
                ffma2(acc[p][3], ap[p], bd3);
            }
        }
        __syncthreads();
    }
    // epilogue: val = scl*(rstd*acc - rstd*mu*u[j] + w0[j]);  scl=2 for k cols
    float4 uu = *(const float4*)&g_u [col0 + tx*4];
    float4 ww = *(const float4*)&g_w0[col0 + tx*4];
    const float scl = (col0 < 256) ? 2.0f : 1.0f;
    #pragma unroll
    for (int i = 0; i < 8; i++){
        int p = i >> 1, hi = i & 1;
        int row = row0 + ty*8 + i;
        float rs = g_rstd[row];
        float mm = g_mu[row]*rs;
        float4 o;
        o.x = scl*(rs*pickf(acc[p][0], hi) - mm*uu.x + ww.x);
        o.y = scl*(rs*pickf(acc[p][1], hi) - mm*uu.y + ww.y);
        o.z = scl*(rs*pickf(acc[p][2], hi) - mm*uu.z + ww.z);
        o.w = scl*(rs*pickf(acc[p][3], hi) - mm*uu.w + ww.w);
        *(float4*)(g_kv + (size_t)row*512 + col0 + tx*4) = o;
    }
}

// ---------------- q = LN(rep) @ Wq -------------------------------------------
__global__ __launch_bounds__(256) void k_q(const float* __restrict__ Wq,
                                           const float* __restrict__ gam,
                                           const float* __restrict__ bet){
    const int b = blockIdx.x, t = threadIdx.x;
    __shared__ float xn[256];
    __shared__ float red[8];
    float x = g_rep[b*256 + t];
    float s = x;
    #pragma unroll
    for (int o = 16; o; o >>= 1) s += __shfl_xor_sync(0xffffffffu, s, o);
    if ((t & 31) == 0) red[t >> 5] = s;
    __syncthreads();
    if (t < 32){
        float r = (t < 8) ? red[t] : 0.f;
        #pragma unroll
        for (int o = 4; o; o >>= 1) r += __shfl_xor_sync(0xffffffffu, r, o);
        if (t == 0) red[0] = r;
    }
    __syncthreads();
    float mu = red[0]*(1.f/256.f);
    __syncthreads();
    float dv = x - mu;
    s = dv*dv;
    #pragma unroll
    for (int o = 16; o; o >>= 1) s += __shfl_xor_sync(0xffffffffu, s, o);
    if ((t & 31) == 0) red[t >> 5] = s;
    __syncthreads();
    if (t < 32){
        float r = (t < 8) ? red[t] : 0.f;
        #pragma unroll
        for (int o = 4; o; o >>= 1) r += __shfl_xor_sync(0xffffffffu, r, o);
        if (t == 0) red[0] = r;
    }
    __syncthreads();
    float rstd = rsqrtf(red[0]*(1.f/256.f) + 1e-5f);
    xn[t] = dv*rstd*gam[t] + bet[t];
    __syncthreads();
    float acc = 0.f;
    #pragma unroll 8
    for (int c = 0; c < 256; c++) acc += xn[c]*Wq[c*256 + t];
    g_q[b*256 + t] = acc;
}

// ---------------- fused sigmoid attention: one pass over k,v -----------------
__global__ __launch_bounds__(256) void k_att(int last){
    const int h = blockIdx.x, b = blockIdx.y;
    const int t = threadIdx.x, w = t >> 5, lane = t & 31;
    __shared__ float qs[64];
    __shared__ float snum[8][64];
    __shared__ float sden[8];
    __shared__ float sdentot;
    if (t < 64) qs[t] = g_q[b*256 + h*64 + t];
    __syncthreads();
    const float q0 = qs[lane], q1 = qs[lane + 32];
    float n0 = 0.f, n1 = 0.f, den = 0.f;
    const float* base = g_kv + (size_t)b*4096*512 + h*64;
    float* sigout = g_sig + ((size_t)(b*4 + h) << 12);
    #pragma unroll 2
    for (int n = w; n < 4096; n += 8){
        const float* p = base + (size_t)n*512;
        float k0 = p[lane],       k1 = p[lane + 32];
        float v0 = p[256 + lane], v1 = p[288 + lane];
        float d = k0*q0 + k1*q1;
        #pragma unroll
        for (int o = 16; o; o >>= 1) d += __shfl_xor_sync(0xffffffffu, d, o);
        float sg = __fdividef(1.f, 1.f + __expf(-d)) + 1e-8f;
        n0 += sg*v0; n1 += sg*v1;
        if (lane == 0){
            den += sg;
            if (last) sigout[n] = sg;
        }
    }
    snum[w][lane] = n0; snum[w][lane + 32] = n1;
    if (lane == 0) sden[w] = den;
    __syncthreads();
    if (t == 0){
        float s = 0.f;
        #pragma unroll
        for (int i = 0; i < 8; i++) s += sden[i];
        sdentot = s;
        if (last) g_den[b*4 + h] = s;
    }
    __syncthreads();
    if (t < 64){
        float s = 0.f;
        #pragma unroll
        for (int i = 0; i < 8; i++) s += snum[i][t];
        g_att[b*256 + h*64 + t] = s / sdentot;
    }
}

// ---------------- GRU cell ---------------------------------------------------
__global__ __launch_bounds__(256) void k_gru(const float* __restrict__ Wih,
                                             const float* __restrict__ Whh,
                                             const float* __restrict__ bih,
                                             const float* __restrict__ bhh){
    const int b = blockIdx.x, t = threadIdx.x, w = t >> 5, lane = t & 31;
    __shared__ float sa[256], sr[256], gi[768], gh[768];
    sa[t] = g_att[b*256 + t];
    sr[t] = g_rep[b*256 + t];
    __syncthreads();
    const float4 x1 = *(const float4*)&sa[lane*4];
    const float4 x2 = *(const float4*)&sa[128 + lane*4];
    const float4 r1 = *(const float4*)&sr[lane*4];
    const float4 r2 = *(const float4*)&sr[128 + lane*4];
    for (int j = w; j < 768; j += 8){
        const float4* pi = (const float4*)(Wih + j*256);
        const float4* ph = (const float4*)(Whh + j*256);
        float4 wa = pi[lane], wb = pi[lane + 32];
        float4 ha = ph[lane], hb = ph[lane + 32];
        float di = wa.x*x1.x + wa.y*x1.y + wa.z*x1.z + wa.w*x1.w
                 + wb.x*x2.x + wb.y*x2.y + wb.z*x2.z + wb.w*x2.w;
        float dh = ha.x*r1.x + ha.y*r1.y + ha.z*r1.z + ha.w*r1.w
                 + hb.x*r2.x + hb.y*r2.y + hb.z*r2.z + hb.w*r2.w;
        #pragma unroll
        for (int o = 16; o; o >>= 1){
            di += __shfl_xor_sync(0xffffffffu, di, o);
            dh += __shfl_xor_sync(0xffffffffu, dh, o);
        }
        if (lane == 0){ gi[j] = di; gh[j] = dh; }
    }
    __syncthreads();
    float ir = gi[t]       + bih[t],       hr = gh[t]       + bhh[t];
    float iz = gi[256 + t] + bih[256 + t], hz = gh[256 + t] + bhh[256 + t];
    float ig = gi[512 + t] + bih[512 + t], hg = gh[512 + t] + bhh[512 + t];
    float r  = __fdividef(1.f, 1.f + __expf(-(ir + hr)));
    float z  = __fdividef(1.f, 1.f + __expf(-(iz + hz)));
    float gg = tanhf(ig + r*hg);
    g_new[b*256 + t] = (1.f - z)*gg + z*sr[t];
}

// ---------------- residual MLP stage 1: h = relu(LN(new) @ W1) ---------------
__global__ __launch_bounds__(256) void k_mlp1(const float* __restrict__ W1,
                                              const float* __restrict__ gam,
                                              const float* __restrict__ bet){
    const int b = blockIdx.x, t = threadIdx.x;
    __shared__ float xn[256];
    __shared__ float red[8];
    float x = g_new[b*256 + t];
    float s = x;
    #pragma unroll
    for (int o = 16; o; o >>= 1) s += __shfl_xor_sync(0xffffffffu, s, o);
    if ((t & 31) == 0) red[t >> 5] = s;
    __syncthreads();
    if (t < 32){
        float r = (t < 8) ? red[t] : 0.f;
        #pragma unroll
        for (int o = 4; o; o >>= 1) r += __shfl_xor_sync(0xffffffffu, r, o);
        if (t == 0) red[0] = r;
    }
    __syncthreads();
    float mu = red[0]*(1.f/256.f);
    __syncthreads();
    float dv = x - mu;
    s = dv*dv;
    #pragma unroll
    for (int o = 16; o; o >>= 1) s += __shfl_xor_sync(0xffffffffu, s, o);
    if ((t & 31) == 0) red[t >> 5] = s;
    __syncthreads();
    if (t < 32){
        float r = (t < 8) ? red[t] : 0.f;
        #pragma unroll
        for (int o = 4; o; o >>= 1) r += __shfl_xor_sync(0xffffffffu, r, o);
        if (t == 0) red[0] = r;
    }
    __syncthreads();
    float rstd = rsqrtf(red[0]*(1.f/256.f) + 1e-5f);
    xn[t] = dv*rstd*gam[t] + bet[t];
    __syncthreads();
    float a0 = 0.f, a1 = 0.f, a2 = 0.f, a3 = 0.f;
    #pragma unroll 4
    for (int c = 0; c < 256; c++){
        float xv = xn[c];
        const float* wr = W1 + c*1024 + t;
        a0 += xv*wr[0];
        a1 += xv*wr[256];
        a2 += xv*wr[512];
        a3 += xv*wr[768];
    }
    g_hbuf[b*1024 + t]       = fmaxf(a0, 0.f);
    g_hbuf[b*1024 + t + 256] = fmaxf(a1, 0.f);
    g_hbuf[b*1024 + t + 512] = fmaxf(a2, 0.f);
    g_hbuf[b*1024 + t + 768] = fmaxf(a3, 0.f);
}

// ---------------- MLP stage 2: rep = new + h @ W2 + b2 -----------------------
__global__ __launch_bounds__(256) void k_mlp2(const float* __restrict__ W2,
                                              const float* __restrict__ b2){
    const int b = blockIdx.x, t = threadIdx.x;
    __shared__ float sh[1024];
    #pragma unroll
    for (int i = 0; i < 4; i++) sh[t + i*256] = g_hbuf[b*1024 + t + i*256];
    __syncthreads();
    float acc = 0.f;
    #pragma unroll 8
    for (int c = 0; c < 1024; c++) acc += sh[c]*W2[c*256 + t];
    g_rep[b*256 + t] = g_new[b*256 + t] + acc + b2[t];
}

// ---------------- outputs ----------------------------------------------------
__global__ void k_wsum(float* __restrict__ out){
    int i = blockIdx.x*256 + threadIdx.x;     // 524288 = B*N
    int b = i >> 12, n = i & 4095;
    float s = 0.f;
    #pragma unroll
    for (int h = 0; h < 4; h++)
        s += g_sig[((size_t)(b*4 + h) << 12) + n] / g_den[b*4 + h];
    out[32768 + i] = s;
}

__global__ void k_wrep(float* __restrict__ out){
    int i = blockIdx.x*256 + threadIdx.x;     // 32768
    out[i] = g_rep[i];
}

// ---------------- launch -----------------------------------------------------
extern "C" void kernel_launch(void* const* d_in, const int* in_sizes, int n_in,
                              void* d_out, int out_size){
    const float* inputs      = (const float*)d_in[0];
    const float* eps         = (const float*)d_in[1];
    const float* init_mu     = (const float*)d_in[2];
    const float* init_logvar = (const float*)d_in[3];
    const float* Wk          = (const float*)d_in[4];
    const float* Wv          = (const float*)d_in[5];
    const float* Wq          = (const float*)d_in[6];
    const float* ln_in_g     = (const float*)d_in[7];
    const float* ln_in_b     = (const float*)d_in[8];
    const float* ln_slot_g   = (const float*)d_in[9];
    const float* ln_slot_b   = (const float*)d_in[10];
    const float* ln_res_g    = (const float*)d_in[11];
    const float* ln_res_b    = (const float*)d_in[12];
    const float* gru_Wih     = (const float*)d_in[13];
    const float* gru_Whh     = (const float*)d_in[14];
    const float* gru_bih     = (const float*)d_in[15];
    const float* gru_bhh     = (const float*)d_in[16];
    const float* mlp_W1      = (const float*)d_in[17];
    const float* mlp_W2      = (const float*)d_in[18];
    const float* mlp_b2      = (const float*)d_in[19];
    float* out = (float*)d_out;

    k_prep<<<2, 256>>>(Wk, Wv, ln_in_g, ln_in_b);
    k_rep0<<<128, 256>>>(eps, init_mu, init_logvar);
    k_rowstats<<<ROWS/8, 256>>>((const float4*)inputs);
    k_gemm_kv<<<dim3(8, 4096), 256>>>(inputs);

    for (int s = 0; s < 4; s++){
        k_q<<<128, 256>>>(Wq, ln_slot_g, ln_slot_b);
        k_att<<<dim3(4, 128), 256>>>(s == 3 ? 1 : 0);
        k_gru<<<128, 256>>>(gru_Wih, gru_Whh, gru_bih, gru_bhh);
        k_mlp1<<<128, 256>>>(mlp_W1, ln_res_g, ln_res_b);
        k_mlp2<<<128, 256>>>(mlp_W2, mlp_b2);
    }

    k_wsum<<<2048, 256>>>(out);
    k_wrep<<<128, 256>>>(out);
}

// round 4
// speedup vs baseline: 2.8608x; 2.8608x over previous
#include <cuda_runtime.h>
#include <cstdint>

// Problem constants
#define BATCH   128
#define NP      4096
#define DIN     256
#define DM      256
#define HIDN    1024
#define CHUNKS  16          // n-chunks per batch in the big pass
#define PSTRIDE 1040        // floats per partial record (1024 Y + 8 scalars, padded)

// ---------------- scratch (device globals: no allocations allowed) ----------
__device__ float g_WkT[256*256];           // Wk transposed [j][c]
__device__ float g_cg[BATCH*4*256];        // per-(b,h) folded logit vector g ⊙ c
__device__ float g_uc[BATCH*4];            // Σ_c cg
__device__ float g_w0c[BATCH*4];           // Σ_c bias_c * c
__device__ float g_part[BATCH*CHUNKS*PSTRIDE];
__device__ float g_rep[BATCH*DM];
__device__ float g_sig[BATCH*4*NP];        // last-step sigmoids (+eps)
__device__ float g_den[BATCH*4];

// ---------------- rep init: reparameterized latent ---------------------------
__global__ void k_rep0(const float* __restrict__ eps, const float* __restrict__ mu0,
                       const float* __restrict__ lv){
    int i = blockIdx.x*256 + threadIdx.x;            // 32768
    int d = i & 255;
    g_rep[i] = mu0[d] + __expf(0.5f*lv[d])*eps[i];
}

// ---------------- one-time: transpose Wk -------------------------------------
__global__ void k_prepT(const float* __restrict__ Wk){
    int j = blockIdx.x, c = threadIdx.x;
    g_WkT[j*256 + c] = Wk[c*256 + j];
}

// ---------------- per step: q = LN(rep)@Wq, then c/cg/uc/w0c -----------------
__global__ __launch_bounds__(256) void k_qc(const float* __restrict__ Wq,
                                            const float* __restrict__ gs,
                                            const float* __restrict__ bs,
                                            const float* __restrict__ gin,
                                            const float* __restrict__ bin){
    const int b = blockIdx.x, t = threadIdx.x, w = t >> 5, lane = t & 31;
    __shared__ __align__(16) float xn[256];
    __shared__ __align__(16) float qS[256];
    __shared__ float red[8];
    __shared__ float redq[8][8];

    // ---- LN(rep)
    float x = g_rep[b*256 + t];
    float s = x;
    #pragma unroll
    for (int o = 16; o; o >>= 1) s += __shfl_xor_sync(0xffffffffu, s, o);
    if (lane == 0) red[w] = s;
    __syncthreads();
    if (t < 32){
        float r = (t < 8) ? red[t] : 0.f;
        #pragma unroll
        for (int o = 4; o; o >>= 1) r += __shfl_xor_sync(0xffffffffu, r, o);
        if (t == 0) red[0] = r;
    }
    __syncthreads();
    float mu = red[0]*(1.f/256.f);
    __syncthreads();
    float dv = x - mu;
    s = dv*dv;
    #pragma unroll
    for (int o = 16; o; o >>= 1) s += __shfl_xor_sync(0xffffffffu, s, o);
    if (lane == 0) red[w] = s;
    __syncthreads();
    if (t < 32){
        float r = (t < 8) ? red[t] : 0.f;
        #pragma unroll
        for (int o = 4; o; o >>= 1) r += __shfl_xor_sync(0xffffffffu, r, o);
        if (t == 0) red[0] = r;
    }
    __syncthreads();
    float rstd = rsqrtf(red[0]*(1.f/256.f) + 1e-5f);
    xn[t] = dv*rstd*gs[t] + bs[t];
    __syncthreads();
    // ---- q = xn @ Wq
    float acc = 0.f;
    #pragma unroll 8
    for (int c = 0; c < 256; c++) acc += xn[c]*Wq[c*256 + t];
    qS[t] = acc;
    __syncthreads();
    // ---- c_h = 2 * Wk_h @ q_h  (per thread: one c-row, all 4 heads)
    float ch[4] = {0.f, 0.f, 0.f, 0.f};
    #pragma unroll 4
    for (int j = 0; j < 256; j++)
        ch[j >> 6] += g_WkT[j*256 + t]*qS[j];
    float ucp[4], w0p[4];
    const float gt = gin[t], bt = bin[t];
    #pragma unroll
    for (int h = 0; h < 4; h++){
        float cv = 2.f*ch[h];
        float cgv = gt*cv;
        g_cg[b*1024 + h*256 + t] = cgv;
        ucp[h] = cgv;
        w0p[h] = bt*cv;
    }
    // block-reduce 8 scalars
    #pragma unroll
    for (int h = 0; h < 4; h++){
        #pragma unroll
        for (int o = 16; o; o >>= 1){
            ucp[h] += __shfl_xor_sync(0xffffffffu, ucp[h], o);
            w0p[h] += __shfl_xor_sync(0xffffffffu, w0p[h], o);
        }
    }
    if (lane == 0){
        #pragma unroll
        for (int h = 0; h < 4; h++){ redq[w][h] = ucp[h]; redq[w][4+h] = w0p[h]; }
    }
    __syncthreads();
    if (t < 8){
        float sv = 0.f;
        #pragma unroll
        for (int i = 0; i < 8; i++) sv += redq[i][t];
        if (t < 4) g_uc[b*4 + t] = sv;
        else       g_w0c[b*4 + (t - 4)] = sv;
    }
}

// ---------------- the big fused pass over X ----------------------------------
// Per patch: row-stats + 4 head logits + sigmoid + weighted accumulation.
__device__ __forceinline__ float dot4(float4 a, float4 b){
    return a.x*b.x + a.y*b.y + a.z*b.z + a.w*b.w;
}
__global__ __launch_bounds__(256,2) void k_pass(const float* __restrict__ X, int last){
    const int chunk = blockIdx.x, b = blockIdx.y;
    const int t = threadIdx.x, w = t >> 5, lane = t & 31;

    float4 cg0[4], cg1[4];
    float uc[4], w0[4];
    #pragma unroll
    for (int h = 0; h < 4; h++){
        cg0[h] = *(const float4*)&g_cg[b*1024 + h*256 + 4*lane];
        cg1[h] = *(const float4*)&g_cg[b*1024 + h*256 + 128 + 4*lane];
        uc[h]  = g_uc[b*4 + h];
        w0[h]  = g_w0c[b*4 + h];
    }
    float4 y0[4], y1[4];
    float s2[4] = {0.f,0.f,0.f,0.f}, s3[4] = {0.f,0.f,0.f,0.f};
    #pragma unroll
    for (int h = 0; h < 4; h++){ y0[h] = make_float4(0,0,0,0); y1[h] = make_float4(0,0,0,0); }

    const int n0 = chunk*256 + w*32;
    const float* base = X + ((size_t)b*4096 + n0)*256;
    float* sigout = g_sig + (size_t)b*16384 + n0;

    #pragma unroll 1
    for (int i = 0; i < 32; i++){
        const float4* p = (const float4*)(base + (size_t)i*256);
        float4 x0 = p[lane], x1 = p[lane + 32];
        float sx  = x0.x+x0.y+x0.z+x0.w + x1.x+x1.y+x1.z+x1.w;
        float sxx = dot4(x0,x0) + dot4(x1,x1);
        float d0 = dot4(x0,cg0[0]) + dot4(x1,cg1[0]);
        float d1 = dot4(x0,cg0[1]) + dot4(x1,cg1[1]);
        float d2 = dot4(x0,cg0[2]) + dot4(x1,cg1[2]);
        float d3 = dot4(x0,cg0[3]) + dot4(x1,cg1[3]);
        #pragma unroll
        for (int o = 16; o; o >>= 1){
            sx  += __shfl_xor_sync(0xffffffffu, sx,  o);
            sxx += __shfl_xor_sync(0xffffffffu, sxx, o);
            d0  += __shfl_xor_sync(0xffffffffu, d0,  o);
            d1  += __shfl_xor_sync(0xffffffffu, d1,  o);
            d2  += __shfl_xor_sync(0xffffffffu, d2,  o);
            d3  += __shfl_xor_sync(0xffffffffu, d3,  o);
        }
        float mu   = sx*(1.f/256.f);
        float rstd = rsqrtf(sxx*(1.f/256.f) - mu*mu + 1e-5f);
        float mr   = mu*rstd;
        float dd[4] = {d0, d1, d2, d3};
        float sg[4];
        #pragma unroll
        for (int h = 0; h < 4; h++){
            float lg = rstd*dd[h] - mr*uc[h] + w0[h];
            sg[h] = __fdividef(1.f, 1.f + __expf(-lg)) + 1e-8f;
        }
        #pragma unroll
        for (int h = 0; h < 4; h++){
            float th = sg[h]*rstd;
            y0[h].x += th*x0.x; y0[h].y += th*x0.y; y0[h].z += th*x0.z; y0[h].w += th*x0.w;
            y1[h].x += th*x1.x; y1[h].y += th*x1.y; y1[h].z += th*x1.z; y1[h].w += th*x1.w;
            s2[h]   += th*mu;
            s3[h]   += sg[h];
        }
        if (last && lane < 4){
            float sv = (lane == 0) ? sg[0] : (lane == 1) ? sg[1] : (lane == 2) ? sg[2] : sg[3];
            sigout[lane*4096 + i] = sv;
        }
    }

    // block reduction of partials -> g_part
    __shared__ __align__(16) float accY[8][1024];
    __shared__ float accS[8][8];
    #pragma unroll
    for (int h = 0; h < 4; h++){
        *(float4*)&accY[w][h*256 + 4*lane]       = y0[h];
        *(float4*)&accY[w][h*256 + 128 + 4*lane] = y1[h];
    }
    if (lane == 0){
        #pragma unroll
        for (int h = 0; h < 4; h++){ accS[w][h] = s2[h]; accS[w][4+h] = s3[h]; }
    }
    __syncthreads();
    float* gp = g_part + (size_t)(b*CHUNKS + chunk)*PSTRIDE;
    #pragma unroll
    for (int o = t; o < 1024; o += 256){
        float sv = 0.f;
        #pragma unroll
        for (int i = 0; i < 8; i++) sv += accY[i][o];
        gp[o] = sv;
    }
    if (t < 8){
        float sv = 0.f;
        #pragma unroll
        for (int i = 0; i < 8; i++) sv += accS[i][t];
        gp[1024 + t] = sv;
    }
}

// ---------------- fused post: reduce -> att -> GRU -> MLP -> rep -------------
__global__ __launch_bounds__(256) void k_post(const float* __restrict__ Wv,
        const float* __restrict__ gin, const float* __restrict__ bin,
        const float* __restrict__ Wih, const float* __restrict__ Whh,
        const float* __restrict__ bih, const float* __restrict__ bhh,
        const float* __restrict__ W1,
        const float* __restrict__ gres, const float* __restrict__ bres,
        const float* __restrict__ W2, const float* __restrict__ b2){
    const int b = blockIdx.x, t = threadIdx.x, w = t >> 5, lane = t & 31;
    __shared__ __align__(16) float yS[1024];
    __shared__ float sc[8];
    __shared__ __align__(16) float attS[256];
    __shared__ __align__(16) float srS[256];
    __shared__ float gi[768], gh[768];
    __shared__ __align__(16) float newS[256];
    __shared__ __align__(16) float xnS[256];
    __shared__ __align__(16) float hS[1024];
    __shared__ float red[8];

    // ---- reduce partials over chunks
    const float* gp0 = g_part + (size_t)b*CHUNKS*PSTRIDE;
    #pragma unroll
    for (int o = t; o < 1024; o += 256){
        float sv = 0.f;
        #pragma unroll
        for (int c = 0; c < CHUNKS; c++) sv += gp0[c*PSTRIDE + o];
        yS[o] = sv;
    }
    if (t < 8){
        float sv = 0.f;
        #pragma unroll
        for (int c = 0; c < CHUNKS; c++) sv += gp0[c*PSTRIDE + 1024 + t];
        sc[t] = sv;
        if (t >= 4) g_den[b*4 + (t - 4)] = sv;   // Σσ' (last write wins = final step)
    }
    __syncthreads();
    // ---- y = gin*(A1 - s2_h) + bin*s3_h
    #pragma unroll
    for (int o = t; o < 1024; o += 256){
        int h = o >> 8, c = o & 255;
        yS[o] = gin[c]*(yS[o] - sc[h]) + bin[c]*sc[4 + h];
    }
    __syncthreads();
    // ---- att = (y_h @ Wv_h) / s3_h
    {
        int h = t >> 6;
        float acc = 0.f;
        const float* yh = &yS[h*256];
        #pragma unroll 8
        for (int c = 0; c < 256; c++) acc += yh[c]*Wv[c*256 + t];
        attS[t] = acc / sc[4 + h];
    }
    srS[t] = g_rep[b*256 + t];
    __syncthreads();
    // ---- GRU
    {
        const float4 x1 = *(const float4*)&attS[lane*4];
        const float4 x2 = *(const float4*)&attS[128 + lane*4];
        const float4 r1 = *(const float4*)&srS[lane*4];
        const float4 r2 = *(const float4*)&srS[128 + lane*4];
        for (int j = w; j < 768; j += 8){
            const float4* pi = (const float4*)(Wih + j*256);
            const float4* ph = (const float4*)(Whh + j*256);
            float4 wa = pi[lane], wb = pi[lane + 32];
            float4 ha = ph[lane], hb = ph[lane + 32];
            float di = wa.x*x1.x + wa.y*x1.y + wa.z*x1.z + wa.w*x1.w
                     + wb.x*x2.x + wb.y*x2.y + wb.z*x2.z + wb.w*x2.w;
            float dh = ha.x*r1.x + ha.y*r1.y + ha.z*r1.z + ha.w*r1.w
                     + hb.x*r2.x + hb.y*r2.y + hb.z*r2.z + hb.w*r2.w;
            #pragma unroll
            for (int o = 16; o; o >>= 1){
                di += __shfl_xor_sync(0xffffffffu, di, o);
                dh += __shfl_xor_sync(0xffffffffu, dh, o);
            }
            if (lane == 0){ gi[j] = di; gh[j] = dh; }
        }
    }
    __syncthreads();
    {
        float ir = gi[t]       + bih[t],       hr = gh[t]       + bhh[t];
        float iz = gi[256 + t] + bih[256 + t], hz = gh[256 + t] + bhh[256 + t];
        float ig = gi[512 + t] + bih[512 + t], hg = gh[512 + t] + bhh[512 + t];
        float r  = __fdividef(1.f, 1.f + __expf(-(ir + hr)));
        float z  = __fdividef(1.f, 1.f + __expf(-(iz + hz)));
        float gg = tanhf(ig + r*hg);
        newS[t] = (1.f - z)*gg + z*srS[t];
    }
    __syncthreads();
    // ---- LN_res(new)
    {
        float x = newS[t];
        float s = x;
        #pragma unroll
        for (int o = 16; o; o >>= 1) s += __shfl_xor_sync(0xffffffffu, s, o);
        if (lane == 0) red[w] = s;
        __syncthreads();
        if (t < 32){
            float r = (t < 8) ? red[t] : 0.f;
            #pragma unroll
            for (int o = 4; o; o >>= 1) r += __shfl_xor_sync(0xffffffffu, r, o);
            if (t == 0) red[0] = r;
        }
        __syncthreads();
        float mu = red[0]*(1.f/256.f);
        __syncthreads();
        float dv = x - mu;
        s = dv*dv;
        #pragma unroll
        for (int o = 16; o; o >>= 1) s += __shfl_xor_sync(0xffffffffu, s, o);
        if (lane == 0) red[w] = s;
        __syncthreads();
        if (t < 32){
            float r = (t < 8) ? red[t] : 0.f;
            #pragma unroll
            for (int o = 4; o; o >>= 1) r += __shfl_xor_sync(0xffffffffu, r, o);
            if (t == 0) red[0] = r;
        }
        __syncthreads();
        float rstd = rsqrtf(red[0]*(1.f/256.f) + 1e-5f);
        xnS[t] = dv*rstd*gres[t] + bres[t];
    }
    __syncthreads();
    // ---- h = relu(xn @ W1)
    {
        float a0 = 0.f, a1 = 0.f, a2 = 0.f, a3 = 0.f;
        #pragma unroll 4
        for (int c = 0; c < 256; c++){
            float xv = xnS[c];
            const float* wr = W1 + c*1024 + t;
            a0 += xv*wr[0];
            a1 += xv*wr[256];
            a2 += xv*wr[512];
            a3 += xv*wr[768];
        }
        hS[t]       = fmaxf(a0, 0.f);
        hS[t + 256] = fmaxf(a1, 0.f);
        hS[t + 512] = fmaxf(a2, 0.f);
        hS[t + 768] = fmaxf(a3, 0.f);
    }
    __syncthreads();
    // ---- rep = new + h @ W2 + b2
    {
        float acc = 0.f;
        #pragma unroll 8
        for (int c = 0; c < 1024; c++) acc += hS[c]*W2[c*256 + t];
        g_rep[b*256 + t] = newS[t] + acc + b2[t];
    }
}

// ---------------- outputs ----------------------------------------------------
__global__ void k_wsum(float* __restrict__ out){
    int i = blockIdx.x*256 + threadIdx.x;     // 524288 = B*N
    int b = i >> 12, n = i & 4095;
    float s = 0.f;
    #pragma unroll
    for (int h = 0; h < 4; h++)
        s += g_sig[((size_t)(b*4 + h) << 12) + n] / g_den[b*4 + h];
    out[32768 + i] = s;
}

__global__ void k_wrep(float* __restrict__ out){
    int i = blockIdx.x*256 + threadIdx.x;     // 32768
    out[i] = g_rep[i];
}

// ---------------- launch -----------------------------------------------------
extern "C" void kernel_launch(void* const* d_in, const int* in_sizes, int n_in,
                              void* d_out, int out_size){
    const float* inputs      = (const float*)d_in[0];
    const float* eps         = (const float*)d_in[1];
    const float* init_mu     = (const float*)d_in[2];
    const float* init_logvar = (const float*)d_in[3];
    const float* Wk          = (const float*)d_in[4];
    const float* Wv          = (const float*)d_in[5];
    const float* Wq          = (const float*)d_in[6];
    const float* ln_in_g     = (const float*)d_in[7];
    const float* ln_in_b     = (const float*)d_in[8];
    const float* ln_slot_g   = (const float*)d_in[9];
    const float* ln_slot_b   = (const float*)d_in[10];
    const float* ln_res_g    = (const float*)d_in[11];
    const float* ln_res_b    = (const float*)d_in[12];
    const float* gru_Wih     = (const float*)d_in[13];
    const float* gru_Whh     = (const float*)d_in[14];
    const float* gru_bih     = (const float*)d_in[15];
    const float* gru_bhh     = (const float*)d_in[16];
    const float* mlp_W1      = (const float*)d_in[17];
    const float* mlp_W2      = (const float*)d_in[18];
    const float* mlp_b2      = (const float*)d_in[19];
    float* out = (float*)d_out;

    k_prepT<<<256, 256>>>(Wk);
    k_rep0<<<128, 256>>>(eps, init_mu, init_logvar);

    for (int s = 0; s < 4; s++){
        k_qc<<<128, 256>>>(Wq, ln_slot_g, ln_slot_b, ln_in_g, ln_in_b);
        k_pass<<<dim3(CHUNKS, 128), 256>>>(inputs, s == 3 ? 1 : 0);
        k_post<<<128, 256>>>(Wv, ln_in_g, ln_in_b,
                             gru_Wih, gru_Whh, gru_bih, gru_bhh,
                             mlp_W1, ln_res_g, ln_res_b, mlp_W2, mlp_b2);
    }

    k_wsum<<<2048, 256>>>(out);
    k_wrep<<<128, 256>>>(out);
}